// round 6
// baseline (speedup 1.0000x reference)
#include <cuda_runtime.h>

// B = 16384 samples, D = 2, G = 2500 grid points.
// Y_surf: [B, 2, 2500] f32.  For each b:
//   idx = argmin_g (Ys[b,0,g]-y[b,0])^2 + (Ys[b,1,g]-y[b,1])^2
//   out[b,d] = U_grid[d, idx]
//
// R6: ONE sample per warp (cheap epilogue, low base regs) with a
// guard-free 19-iteration main loop unrolled x4 -> 8 unconditional,
// front-batchable LDG.128 per unrolled body. 625 = 19*32 + 17:
//   k = 0..18 : i = lane + 32k <= 607 < 625  -> valid for ALL lanes
//   tail      : i = lane + 608, valid iff lane <= 16 (one predicated iter)

#define G_CONST 2500
#define G4_CONST 625
#define FULL_ITERS 19
#define WARPS_PER_BLOCK 8

__global__ __launch_bounds__(WARPS_PER_BLOCK * 32)
void lqr_push_kernel6(const float* __restrict__ y,
                      const float* __restrict__ Y_surf,
                      const float* __restrict__ U_grid,
                      float* __restrict__ out,
                      int B)
{
    const int warp = threadIdx.x >> 5;
    const int lane = threadIdx.x & 31;
    const int b = blockIdx.x * WARPS_PER_BLOCK + warp;
    if (b >= B) return;

    const float y0 = __ldg(&y[2 * b + 0]);
    const float y1 = __ldg(&y[2 * b + 1]);

    const size_t row = (size_t)b * (size_t)(2 * G_CONST);
    const float4* __restrict__ r0 = reinterpret_cast<const float4*>(Y_surf + row);
    const float4* __restrict__ r1 = reinterpret_cast<const float4*>(Y_surf + row + G_CONST);

    float best = 3.402823466e38f;
    int   bidx = 0;

    // Main loop: constant trip count, no guards -> unroll 4 gives 8
    // independent LDG.128 that ptxas can hoist to the front of the body.
    #pragma unroll 4
    for (int k = 0; k < FULL_ITERS; ++k) {
        const int i = lane + (k << 5);
        const float4 a = __ldcs(r0 + i);
        const float4 c = __ldcs(r1 + i);
        const int g = i << 2;

        float dx, dz, d2;

        dx = a.x - y0; dz = c.x - y1; d2 = dx*dx + dz*dz;
        if (d2 < best) { best = d2; bidx = g + 0; }

        dx = a.y - y0; dz = c.y - y1; d2 = dx*dx + dz*dz;
        if (d2 < best) { best = d2; bidx = g + 1; }

        dx = a.z - y0; dz = c.z - y1; d2 = dx*dx + dz*dz;
        if (d2 < best) { best = d2; bidx = g + 2; }

        dx = a.w - y0; dz = c.w - y1; d2 = dx*dx + dz*dz;
        if (d2 < best) { best = d2; bidx = g + 3; }
    }

    // Tail: i = lane + 608, valid for lanes 0..16.
    {
        const int i = lane + FULL_ITERS * 32;
        if (i < G4_CONST) {
            const float4 a = __ldcs(r0 + i);
            const float4 c = __ldcs(r1 + i);
            const int g = i << 2;

            float dx, dz, d2;

            dx = a.x - y0; dz = c.x - y1; d2 = dx*dx + dz*dz;
            if (d2 < best) { best = d2; bidx = g + 0; }

            dx = a.y - y0; dz = c.y - y1; d2 = dx*dx + dz*dz;
            if (d2 < best) { best = d2; bidx = g + 1; }

            dx = a.z - y0; dz = c.z - y1; d2 = dx*dx + dz*dz;
            if (d2 < best) { best = d2; bidx = g + 2; }

            dx = a.w - y0; dz = c.w - y1; d2 = dx*dx + dz*dz;
            if (d2 < best) { best = d2; bidx = g + 3; }
        }
    }
    // Per-thread indices strictly increase, so '<' keeps the FIRST minimum.

    // Warp argmin with first-index tie-break (matches jnp.argmin).
    #pragma unroll
    for (int off = 16; off > 0; off >>= 1) {
        const float ov = __shfl_xor_sync(0xffffffffu, best, off);
        const int   oi = __shfl_xor_sync(0xffffffffu, bidx, off);
        if (ov < best || (ov == best && oi < bidx)) { best = ov; bidx = oi; }
    }

    if (lane == 0) {
        out[2 * b + 0] = __ldg(&U_grid[bidx]);
        out[2 * b + 1] = __ldg(&U_grid[G_CONST + bidx]);
    }
}

extern "C" void kernel_launch(void* const* d_in, const int* in_sizes, int n_in,
                              void* d_out, int out_size)
{
    const float* y      = (const float*)d_in[0];   // [B, 2]
    const float* Y_surf = (const float*)d_in[1];   // [B, 2, 2500]
    const float* U_grid = (const float*)d_in[2];   // [2, 2500]
    float* out = (float*)d_out;                    // [B, 2]

    const int B = in_sizes[0] / 2;

    const int threads = WARPS_PER_BLOCK * 32;      // 256
    const int blocks  = (B + WARPS_PER_BLOCK - 1) / WARPS_PER_BLOCK;   // 2048

    lqr_push_kernel6<<<blocks, threads>>>(y, Y_surf, U_grid, out, B);
}